// round 12
// baseline (speedup 1.0000x reference)
#include <cuda_runtime.h>

// Parametric LIF forward — FINAL (converged optimum; verified rounds 6/7/9/10/11).
// float4 per thread, 512 blocks x 256 threads, plain LDG.128/STG.128.
//
// Surface fully bracketed over 11 rounds:
//   width/occ: 2f=48.5us, 4f=38.1-39.2us (BEST), 8f=60us  (concave)
//   MLP x2: neutral. R/W burst phasing: neutral. __ldcs: -29%. CTA size: neutral.
// ~5.7 TB/s is the mixed 50/50 R/W DRAM ceiling; 256 MB traffic is
// irreducible; kernel sits at ~88% of the 8 TB/s spec floor with all
// compute pipes <15% busy.
//
// x: [B=64, T=64, N=8192] fp32. Per channel (b,n), sequential over t:
//   u    = last * sig + x[t]
//   s    = (u >= th) ? 1 : 0
//   last = s ? 0 : u + lamb*(u - last)
//   out[t] = s

#ifndef LIF_B
#define LIF_B 64
#define LIF_T 64
#define LIF_N 8192
#endif

__global__ __launch_bounds__(256) void lif_fwd_kernel(
    const float* __restrict__ x,
    const float* __restrict__ tau_p,
    const float* __restrict__ lamb_p,
    const float* __restrict__ th_p,
    float* __restrict__ out)
{
    constexpr int NV = LIF_N / 4;              // 2048 float4 groups per row
    const int idx = blockIdx.x * blockDim.x + threadIdx.x;
    const int b  = idx >> 11;                  // idx / 2048
    const int nv = idx & (NV - 1);             // idx % 2048

    const float tp   = tau_p[0];
    const float sig  = 1.0f / (1.0f + __expf(-tp));
    const float lamb = lamb_p[0];
    const float th   = th_p[0];

    const float4* __restrict__ xp = reinterpret_cast<const float4*>(x)
                                    + (size_t)b * LIF_T * NV + nv;
    float4* __restrict__ op = reinterpret_cast<float4*>(out)
                              + (size_t)b * LIF_T * NV + nv;

    float l0 = 0.f, l1 = 0.f, l2 = 0.f, l3 = 0.f;

    #pragma unroll 16
    for (int t = 0; t < LIF_T; ++t) {
        const float4 xv = xp[(size_t)t * NV];

        float u0 = fmaf(l0, sig, xv.x);
        float s0 = (u0 >= th) ? 1.0f : 0.0f;
        l0 = (u0 >= th) ? 0.0f : fmaf(lamb, u0 - l0, u0);

        float u1 = fmaf(l1, sig, xv.y);
        float s1 = (u1 >= th) ? 1.0f : 0.0f;
        l1 = (u1 >= th) ? 0.0f : fmaf(lamb, u1 - l1, u1);

        float u2 = fmaf(l2, sig, xv.z);
        float s2 = (u2 >= th) ? 1.0f : 0.0f;
        l2 = (u2 >= th) ? 0.0f : fmaf(lamb, u2 - l2, u2);

        float u3 = fmaf(l3, sig, xv.w);
        float s3 = (u3 >= th) ? 1.0f : 0.0f;
        l3 = (u3 >= th) ? 0.0f : fmaf(lamb, u3 - l3, u3);

        float4 sv;
        sv.x = s0; sv.y = s1; sv.z = s2; sv.w = s3;
        op[(size_t)t * NV] = sv;
    }
}

extern "C" void kernel_launch(void* const* d_in, const int* in_sizes, int n_in,
                              void* d_out, int out_size)
{
    const float* x    = (const float*)d_in[0];
    const float* tau  = (const float*)d_in[1];
    const float* lamb = (const float*)d_in[2];
    const float* th   = (const float*)d_in[3];
    float* out = (float*)d_out;

    constexpr int NV = LIF_N / 4;
    constexpr int total = LIF_B * NV;          // 131072 threads
    constexpr int block = 256;
    lif_fwd_kernel<<<total / block, block>>>(x, tau, lamb, th, out);
}